// round 17
// baseline (speedup 1.0000x reference)
#include <cuda_runtime.h>
#include <cuda_fp16.h>
#include <cstdint>
#include <math.h>

// ---------------- problem dims ----------------
#define BB    1024
#define DIN   2048
#define DINT  8192
#define NGIN  16
#define NGINT 64

// ---------------- scratch (device globals) ----------------
__device__ __half g_rotd_h[NGINT * 128 * 128];
__device__ __half g_Wg   [DINT * DIN];
__device__ __half g_Wu   [DINT * DIN];
__device__ __half g_Wd   [DIN * DINT];
__device__ __half g_xrg  [BB * DIN];
__device__ __half g_xru  [BB * DIN];
__device__ __half g_gate [BB * DINT];
__device__ __half g_hr   [BB * DINT];
__device__ float  g_part [2 * BB * DIN];

__device__ __forceinline__ uint32_t pack2(int v, const float* lut, float s) {
    __half2 h = __floats2half2_rn(lut[v & 15] * s, lut[(v >> 4) & 15] * s);
    return *reinterpret_cast<uint32_t*>(&h);
}

__global__ void k_reduce2(const float4* __restrict__ p0, const float4* __restrict__ p1,
                          const float* __restrict__ bias, float4* __restrict__ out,
                          int n4, int ldc4) {
    int i = blockIdx.x * blockDim.x + threadIdx.x;
    if (i >= n4) return;
    float4 a = p0[i], b = p1[i];
    int c4 = i % ldc4;
    const float4 bv = reinterpret_cast<const float4*>(bias)[c4];
    float4 o;
    o.x = a.x + b.x + bv.x;
    o.y = a.y + b.y + bv.y;
    o.z = a.z + b.z + bv.z;
    o.w = a.w + b.w + bv.w;
    out[i] = o;
}

// ---------------- GEMM machinery ----------------
#define STG2   3
#define STAGE_H (128 * 64)
#define SMEM_G2 (STG2 * STAGE_H * 2 * 2)   // 98304 B

#define DQ_BPM   2048
#define DQ_INT4  ((long)DQ_BPM * 256)
#define CVT_BPM  256                        // rotd convert backfill blocks
#define CVT_N3   (NGINT * 128 * 128 / 4)    // 262144 float4

__device__ __forceinline__ void cpasync16(void* s, const void* g) {
    uint32_t sa = (uint32_t)__cvta_generic_to_shared(s);
    asm volatile("cp.async.cg.shared.global [%0], [%1], 16;\n" :: "r"(sa), "l"(g));
}
__device__ __forceinline__ void ldm4(uint32_t& r0, uint32_t& r1, uint32_t& r2, uint32_t& r3,
                                     const void* p) {
    uint32_t a = (uint32_t)__cvta_generic_to_shared(p);
    asm volatile("ldmatrix.sync.aligned.m8n8.x4.shared.b16 {%0,%1,%2,%3}, [%4];"
                 : "=r"(r0), "=r"(r1), "=r"(r2), "=r"(r3) : "r"(a));
}
__device__ __forceinline__ void mma16816(float* c, const uint32_t* a, const uint32_t* b) {
    asm volatile(
        "mma.sync.aligned.m16n8k16.row.col.f32.f16.f16.f32 "
        "{%0,%1,%2,%3}, {%4,%5,%6,%7}, {%8,%9}, {%0,%1,%2,%3};"
        : "+f"(c[0]), "+f"(c[1]), "+f"(c[2]), "+f"(c[3])
        : "r"(a[0]), "r"(a[1]), "r"(a[2]), "r"(a[3]), "r"(b[0]), "r"(b[1]));
}

// dequant block body: 256 threads x 4 int4 chunks -> 8192 fp16 weights
__device__ __forceinline__ void dequant_block(const int* __restrict__ packed,
                                              const float* __restrict__ norms,
                                              __half* __restrict__ out,
                                              int K, int bb, int tid, const float* lut) {
    const int Kh = K >> 1;
    const int ng = K >> 7;
    long base = (long)bb * 256 + tid;
    int4 pk[4];
    float s[4];
    long idx[4];
#pragma unroll
    for (int p = 0; p < 4; p++) {
        idx[p] = base + p * DQ_INT4;
        pk[p] = reinterpret_cast<const int4*>(packed)[idx[p]];
        long p0 = idx[p] * 4;
        int n  = (int)(p0 / Kh);
        int k0 = (int)(p0 % Kh) * 2;
        s[p] = norms[(long)n * ng + (k0 >> 7)];
    }
#pragma unroll
    for (int p = 0; p < 4; p++) {
        uint4 o;
        o.x = pack2(pk[p].x, lut, s[p]);
        o.y = pack2(pk[p].y, lut, s[p]);
        o.z = pack2(pk[p].z, lut, s[p]);
        o.w = pack2(pk[p].w, lut, s[p]);
        reinterpret_cast<uint4*>(out)[idx[p]] = o;
    }
}

// EPI: 4 = raw float out (split-K partial).
template<int EPI>
__global__ void __launch_bounds__(256, 2)
k_gemm(const __half* __restrict__ A, const __half* __restrict__ B,
       const float* __restrict__ bias, const __half* __restrict__ aux,
       void* __restrict__ C,
       int M, int N, int K, int lda, int ldb, int ldc,
       int aColOff, int bBatch, int cColOff, int cBatch) {
    extern __shared__ __half sm[];
    __half* As = sm;
    __half* Bs = sm + STG2 * STAGE_H;

    const int tid = threadIdx.x, lane = tid & 31, wid = tid >> 5;
    const int wm = wid >> 2, wn = wid & 3;
    const int m0 = blockIdx.x * 128, n0 = blockIdx.y * 128;
    const __half* Ab = A + (size_t)blockIdx.z * aColOff;
    const __half* Bb = B + (size_t)blockIdx.z * bBatch;
    const int kt = K >> 6;

    float acc[4][4][4];
#pragma unroll
    for (int i = 0; i < 4; i++)
#pragma unroll
        for (int j = 0; j < 4; j++)
#pragma unroll
            for (int k = 0; k < 4; k++) acc[i][j][k] = 0.f;

    const int rw = tid >> 3;
    const int kc = tid & 7;

    auto issue = [&](int t) {
        int slot = t % STG2;
        __half* as = As + slot * STAGE_H;
        __half* bs = Bs + slot * STAGE_H;
        int k0 = t << 6;
#pragma unroll
        for (int j = 0; j < 4; j++) {
            int row = rw + 32 * j;
            uint32_t so = (uint32_t)row * 64 + (uint32_t)((kc ^ (row & 7)) * 8);
            cpasync16(as + so, Ab + (size_t)(m0 + row) * lda + k0 + kc * 8);
            cpasync16(bs + so, Bb + (size_t)(n0 + row) * ldb + k0 + kc * 8);
        }
    };

    issue(0);
    asm volatile("cp.async.commit_group;");
    if (1 < kt) issue(1);
    asm volatile("cp.async.commit_group;");

    for (int t = 0; t < kt; t++) {
        asm volatile("cp.async.wait_group %0;" :: "n"(1));
        __syncthreads();
        int nt = t + 2;
        if (nt < kt) issue(nt);
        asm volatile("cp.async.commit_group;");

        int slot = t % STG2;
        const __half* as = As + slot * STAGE_H;
        const __half* bs = Bs + slot * STAGE_H;
#pragma unroll
        for (int kk = 0; kk < 4; kk++) {
            uint32_t af[4][4], bf[4][2];
#pragma unroll
            for (int mi = 0; mi < 4; mi++) {
                int ar = wm * 64 + mi * 16 + (lane & 15);
                int ch = kk * 2 + (lane >> 4);
                const __half* p = as + ar * 64 + ((ch ^ (ar & 7)) * 8);
                ldm4(af[mi][0], af[mi][1], af[mi][2], af[mi][3], p);
            }
#pragma unroll
            for (int nb = 0; nb < 2; nb++) {
                int br = wn * 32 + nb * 16 + (lane & 7) + ((lane >> 4) << 3);
                int ch = kk * 2 + ((lane >> 3) & 1);
                const __half* p = bs + br * 64 + ((ch ^ (br & 7)) * 8);
                uint32_t q0, q1, q2, q3;
                ldm4(q0, q1, q2, q3, p);
                bf[nb * 2][0] = q0; bf[nb * 2][1] = q1;
                bf[nb * 2 + 1][0] = q2; bf[nb * 2 + 1][1] = q3;
            }
#pragma unroll
            for (int mi = 0; mi < 4; mi++)
#pragma unroll
                for (int ni = 0; ni < 4; ni++)
                    mma16816(acc[mi][ni], af[mi], bf[ni]);
        }
    }

    const int crow = wm * 64 + (lane >> 2);
    const int ccol = wn * 32 + (lane & 3) * 2;
#pragma unroll
    for (int mi = 0; mi < 4; mi++) {
#pragma unroll
        for (int ni = 0; ni < 4; ni++) {
            int gr = m0 + crow + mi * 16;
            int gc = n0 + ccol + ni * 8 + blockIdx.z * cColOff;
            float v0 = acc[mi][ni][0], v1 = acc[mi][ni][1];
            float v2 = acc[mi][ni][2], v3 = acc[mi][ni][3];
            if (EPI == 4) {
                float* Cf = (float*)C + (size_t)blockIdx.z * cBatch;
                *reinterpret_cast<float2*>(&Cf[(size_t)gr * ldc + gc])       = make_float2(v0, v1);
                *reinterpret_cast<float2*>(&Cf[(size_t)(gr + 8) * ldc + gc]) = make_float2(v2, v3);
            } else {
                __half* Ch = (__half*)C;
                *reinterpret_cast<__half2*>(&Ch[(size_t)gr * ldc + gc])       = __floats2half2_rn(v0, v1);
                *reinterpret_cast<__half2*>(&Ch[(size_t)(gr + 8) * ldc + gc]) = __floats2half2_rn(v2, v3);
            }
        }
    }
}

// ---------------- gate GEMM + Wu/Wd dequant in ONE launch ----------------
__global__ void __launch_bounds__(256, 2)
k_gate_mix(const __half* __restrict__ xrg, const __half* __restrict__ Wg,
           const float* __restrict__ gbias, __half* __restrict__ gateh,
           const int* __restrict__ upk, const int* __restrict__ dpk,
           const float* __restrict__ cb,
           const float* __restrict__ un, const float* __restrict__ dn,
           __half* __restrict__ wu, __half* __restrict__ wd) {
    extern __shared__ __half sm[];
    const int tid = threadIdx.x;

    if (blockIdx.x >= 512) {
        float* lut = (float*)sm;
        if (tid < 16) lut[tid] = cb[tid] * 0.08838834764831845f;
        __syncthreads();
        int j = blockIdx.x - 512;
        int z = j / DQ_BPM, bb = j % DQ_BPM;
        if (z == 0) dequant_block(upk, un, wu, DIN,  bb, tid, lut);
        else        dequant_block(dpk, dn, wd, DINT, bb, tid, lut);
        return;
    }

    __half* As = sm;
    __half* Bs = sm + STG2 * STAGE_H;

    const int lane = tid & 31, wid = tid >> 5;
    const int wm = wid >> 2, wn = wid & 3;
    const int m0 = (blockIdx.x & 7) * 128, n0 = (blockIdx.x >> 3) * 128;
    const int kt = DIN >> 6;
    const int rw = tid >> 3, kc = tid & 7;

    float acc[4][4][4];
#pragma unroll
    for (int i = 0; i < 4; i++)
#pragma unroll
        for (int j = 0; j < 4; j++)
#pragma unroll
            for (int k = 0; k < 4; k++) acc[i][j][k] = 0.f;

    auto issue = [&](int t) {
        int slot = t % STG2;
        __half* as = As + slot * STAGE_H;
        __half* bs = Bs + slot * STAGE_H;
        int k0 = t << 6;
#pragma unroll
        for (int j = 0; j < 4; j++) {
            int row = rw + 32 * j;
            uint32_t so = (uint32_t)row * 64 + (uint32_t)((kc ^ (row & 7)) * 8);
            cpasync16(as + so, xrg + (size_t)(m0 + row) * DIN + k0 + kc * 8);
            cpasync16(bs + so, Wg  + (size_t)(n0 + row) * DIN + k0 + kc * 8);
        }
    };

    issue(0);
    asm volatile("cp.async.commit_group;");
    issue(1);
    asm volatile("cp.async.commit_group;");

    for (int t = 0; t < kt; t++) {
        asm volatile("cp.async.wait_group %0;" :: "n"(1));
        __syncthreads();
        int nt = t + 2;
        if (nt < kt) issue(nt);
        asm volatile("cp.async.commit_group;");

        int slot = t % STG2;
        const __half* as = As + slot * STAGE_H;
        const __half* bs = Bs + slot * STAGE_H;
#pragma unroll
        for (int kk = 0; kk < 4; kk++) {
            uint32_t af[4][4], bf[4][2];
#pragma unroll
            for (int mi = 0; mi < 4; mi++) {
                int ar = wm * 64 + mi * 16 + (lane & 15);
                int ch = kk * 2 + (lane >> 4);
                const __half* p = as + ar * 64 + ((ch ^ (ar & 7)) * 8);
                ldm4(af[mi][0], af[mi][1], af[mi][2], af[mi][3], p);
            }
#pragma unroll
            for (int nb = 0; nb < 2; nb++) {
                int br = wn * 32 + nb * 16 + (lane & 7) + ((lane >> 4) << 3);
                int ch = kk * 2 + ((lane >> 3) & 1);
                const __half* p = bs + br * 64 + ((ch ^ (br & 7)) * 8);
                uint32_t q0, q1, q2, q3;
                ldm4(q0, q1, q2, q3, p);
                bf[nb * 2][0] = q0; bf[nb * 2][1] = q1;
                bf[nb * 2 + 1][0] = q2; bf[nb * 2 + 1][1] = q3;
            }
#pragma unroll
            for (int mi = 0; mi < 4; mi++)
#pragma unroll
                for (int ni = 0; ni < 4; ni++)
                    mma16816(acc[mi][ni], af[mi], bf[ni]);
        }
    }

    const int crow = wm * 64 + (lane >> 2);
    const int ccol = wn * 32 + (lane & 3) * 2;
#pragma unroll
    for (int mi = 0; mi < 4; mi++) {
#pragma unroll
        for (int ni = 0; ni < 4; ni++) {
            int gr = m0 + crow + mi * 16;
            int gc = n0 + ccol + ni * 8;
            float b0 = gbias[gc], b1 = gbias[gc + 1];
            float v0 = acc[mi][ni][0] + b0, v1 = acc[mi][ni][1] + b1;
            float v2 = acc[mi][ni][2] + b0, v3 = acc[mi][ni][3] + b1;
            *reinterpret_cast<__half2*>(&gateh[(size_t)gr * DINT + gc]) =
                __floats2half2_rn(v0, v1);
            *reinterpret_cast<__half2*>(&gateh[(size_t)(gr + 8) * DINT + gc]) =
                __floats2half2_rn(v2, v3);
        }
    }
}

// ---------------- fused up + SwiGLU + h-rotation ----------------
__global__ void __launch_bounds__(256, 2)
k_uprot(const __half* __restrict__ xru, const __half* __restrict__ Wu,
        const float* __restrict__ ubias, const __half* __restrict__ gateh,
        const __half* __restrict__ rdh, __half* __restrict__ hr) {
    extern __shared__ __half sm[];
    __half* As = sm;
    __half* Bs = sm + STG2 * STAGE_H;

    const int tid = threadIdx.x, lane = tid & 31, wid = tid >> 5;
    const int wm = wid >> 2, wn = wid & 3;
    const int m0 = blockIdx.x * 128, n0 = blockIdx.y * 128;
    const int g  = blockIdx.y;
    const int kt = DIN >> 6;
    const int rw = tid >> 3, kc = tid & 7;

    float acc[4][4][4];
#pragma unroll
    for (int i = 0; i < 4; i++)
#pragma unroll
        for (int j = 0; j < 4; j++)
#pragma unroll
            for (int k = 0; k < 4; k++) acc[i][j][k] = 0.f;

    auto issue = [&](int t) {
        int slot = t % STG2;
        __half* as = As + slot * STAGE_H;
        __half* bs = Bs + slot * STAGE_H;
        int k0 = t << 6;
#pragma unroll
        for (int j = 0; j < 4; j++) {
            int row = rw + 32 * j;
            uint32_t so = (uint32_t)row * 64 + (uint32_t)((kc ^ (row & 7)) * 8);
            cpasync16(as + so, xru + (size_t)(m0 + row) * DIN + k0 + kc * 8);
            cpasync16(bs + so, Wu  + (size_t)(n0 + row) * DIN + k0 + kc * 8);
        }
    };

    issue(0);
    asm volatile("cp.async.commit_group;");
    issue(1);
    asm volatile("cp.async.commit_group;");

    for (int t = 0; t < kt; t++) {
        asm volatile("cp.async.wait_group %0;" :: "n"(1));
        __syncthreads();
        int nt = t + 2;
        if (nt < kt) issue(nt);
        asm volatile("cp.async.commit_group;");

        int slot = t % STG2;
        const __half* as = As + slot * STAGE_H;
        const __half* bs = Bs + slot * STAGE_H;
#pragma unroll
        for (int kk = 0; kk < 4; kk++) {
            uint32_t af[4][4], bf[4][2];
#pragma unroll
            for (int mi = 0; mi < 4; mi++) {
                int ar = wm * 64 + mi * 16 + (lane & 15);
                int ch = kk * 2 + (lane >> 4);
                const __half* p = as + ar * 64 + ((ch ^ (ar & 7)) * 8);
                ldm4(af[mi][0], af[mi][1], af[mi][2], af[mi][3], p);
            }
#pragma unroll
            for (int nb = 0; nb < 2; nb++) {
                int br = wn * 32 + nb * 16 + (lane & 7) + ((lane >> 4) << 3);
                int ch = kk * 2 + ((lane >> 3) & 1);
                const __half* p = bs + br * 64 + ((ch ^ (br & 7)) * 8);
                uint32_t q0, q1, q2, q3;
                ldm4(q0, q1, q2, q3, p);
                bf[nb * 2][0] = q0; bf[nb * 2][1] = q1;
                bf[nb * 2 + 1][0] = q2; bf[nb * 2 + 1][1] = q3;
            }
#pragma unroll
            for (int mi = 0; mi < 4; mi++)
#pragma unroll
                for (int ni = 0; ni < 4; ni++)
                    mma16816(acc[mi][ni], af[mi], bf[ni]);
        }
    }
    __syncthreads();

    {
        int row = tid >> 1, hf = tid & 1;
        const __half* src = rdh + (size_t)g * (128 * 128) + row * 128 + hf * 64;
        uint32_t base = (uint32_t)row * 64;
#pragma unroll
        for (int c = 0; c < 8; c++) {
            uint32_t so = (uint32_t)hf * STAGE_H + base + (uint32_t)((c ^ (row & 7)) * 8);
            cpasync16(Bs + so, src + c * 8);
        }
    }
    asm volatile("cp.async.commit_group;");

    const int crow = wm * 64 + (lane >> 2);
    const int ccol = wn * 32 + (lane & 3) * 2;
#pragma unroll
    for (int mi = 0; mi < 4; mi++) {
#pragma unroll
        for (int ni = 0; ni < 4; ni++) {
            int r  = crow + mi * 16;
            int c  = ccol + ni * 8;
            int gr = m0 + r;
            int gc = n0 + c;
            float b0 = ubias[gc], b1 = ubias[gc + 1];
            float v0 = acc[mi][ni][0] + b0, v1 = acc[mi][ni][1] + b1;
            float v2 = acc[mi][ni][2] + b0, v3 = acc[mi][ni][3] + b1;
            __half2 ga = *reinterpret_cast<const __half2*>(&gateh[(size_t)gr * DINT + gc]);
            __half2 gb = *reinterpret_cast<const __half2*>(&gateh[(size_t)(gr + 8) * DINT + gc]);
            float g0 = __half2float(ga.x), g1 = __half2float(ga.y);
            float g2 = __half2float(gb.x), g3 = __half2float(gb.y);
            v0 *= g0 / (1.f + __expf(-g0));
            v1 *= g1 / (1.f + __expf(-g1));
            v2 *= g2 / (1.f + __expf(-g2));
            v3 *= g3 / (1.f + __expf(-g3));
            int slab = c >> 6, cc = c & 63, chunk = cc >> 3, win = cc & 7;
            uint32_t off = (uint32_t)slab * STAGE_H + ((uint32_t)(chunk ^ (r & 7)) * 8) + win;
            *reinterpret_cast<__half2*>(&As[off + (uint32_t)r * 64]) =
                __floats2half2_rn(v0, v1);
            *reinterpret_cast<__half2*>(&As[off + (uint32_t)(r + 8) * 64]) =
                __floats2half2_rn(v2, v3);
        }
    }
    asm volatile("cp.async.wait_group %0;" :: "n"(0));
    __syncthreads();

#pragma unroll
    for (int i = 0; i < 4; i++)
#pragma unroll
        for (int j = 0; j < 4; j++)
#pragma unroll
            for (int k = 0; k < 4; k++) acc[i][j][k] = 0.f;

#pragma unroll
    for (int t2 = 0; t2 < 2; t2++) {
        const __half* as = As + t2 * STAGE_H;
        const __half* bs = Bs + t2 * STAGE_H;
#pragma unroll
        for (int kk = 0; kk < 4; kk++) {
            uint32_t af[4][4], bf[4][2];
#pragma unroll
            for (int mi = 0; mi < 4; mi++) {
                int ar = wm * 64 + mi * 16 + (lane & 15);
                int ch = kk * 2 + (lane >> 4);
                const __half* p = as + ar * 64 + ((ch ^ (ar & 7)) * 8);
                ldm4(af[mi][0], af[mi][1], af[mi][2], af[mi][3], p);
            }
#pragma unroll
            for (int nb = 0; nb < 2; nb++) {
                int br = wn * 32 + nb * 16 + (lane & 7) + ((lane >> 4) << 3);
                int ch = kk * 2 + ((lane >> 3) & 1);
                const __half* p = bs + br * 64 + ((ch ^ (br & 7)) * 8);
                uint32_t q0, q1, q2, q3;
                ldm4(q0, q1, q2, q3, p);
                bf[nb * 2][0] = q0; bf[nb * 2][1] = q1;
                bf[nb * 2 + 1][0] = q2; bf[nb * 2 + 1][1] = q3;
            }
#pragma unroll
            for (int mi = 0; mi < 4; mi++)
#pragma unroll
                for (int ni = 0; ni < 4; ni++)
                    mma16816(acc[mi][ni], af[mi], bf[ni]);
        }
    }

#pragma unroll
    for (int mi = 0; mi < 4; mi++) {
#pragma unroll
        for (int ni = 0; ni < 4; ni++) {
            int gr = m0 + crow + mi * 16;
            int gc = n0 + ccol + ni * 8;
            *reinterpret_cast<__half2*>(&hr[(size_t)gr * DINT + gc]) =
                __floats2half2_rn(acc[mi][ni][0], acc[mi][ni][1]);
            *reinterpret_cast<__half2*>(&hr[(size_t)(gr + 8) * DINT + gc]) =
                __floats2half2_rn(acc[mi][ni][2], acc[mi][ni][3]);
        }
    }
}

// ---------------- phase 1: x-rotations (fp32 inline-convert) + Wg dequant + rotd convert ----------------
// blocks [0,256): rot branch. [256, 256+2048): Wg dequant. [2304, 2304+256): rotd->rdh convert.
__global__ void __launch_bounds__(256, 2)
k_phase1(const float* __restrict__ xf,
         const float* __restrict__ rotg, const float* __restrict__ rotu,
         __half* __restrict__ xrg, __half* __restrict__ xru,
         const int* __restrict__ gp, const float* __restrict__ cb,
         const float* __restrict__ gn, __half* __restrict__ wg,
         const float* __restrict__ rotd, __half* __restrict__ rdh) {
    extern __shared__ __half sm[];
    const int tid = threadIdx.x;

    if (blockIdx.x >= 256 + DQ_BPM) {
        // rotd -> rdh fp16 convert (4 float4 per thread, same rounding as before)
        int bb = blockIdx.x - 256 - DQ_BPM;
        long base = (long)bb * 1024 + tid * 4;
        const float4* in = (const float4*)rotd;
        __half2* out = (__half2*)rdh;
#pragma unroll
        for (int p = 0; p < 4; p++) {
            long j = base + p;
            float4 v = in[j];
            out[2 * j]     = __floats2half2_rn(v.x, v.y);
            out[2 * j + 1] = __floats2half2_rn(v.z, v.w);
        }
        return;
    }
    if (blockIdx.x >= 256) {
        float* lut = (float*)sm;
        if (tid < 16) lut[tid] = cb[tid] * 0.08838834764831845f;
        __syncthreads();
        dequant_block(gp, gn, wg, DIN, blockIdx.x - 256, tid, lut);
        return;
    }

    // ---- rotation branch: resident-tile GEMM, fp32 inputs converted inline ----
    // smem: A tile 2 slabs (32 KB) then B tile 2 slabs (32 KB)
    __half* At = sm;
    __half* Bt = sm + 2 * STAGE_H;

    const int path = blockIdx.x >> 7;
    const int r    = blockIdx.x & 127;
    const int m0   = (r & 7) * 128;
    const int grp  = r >> 3;
    const float* Af = xf + grp * 128;                       // column slice of x (fp32)
    const float* Bf = (path ? rotu : rotg) + (size_t)grp * 128 * 128;
    __half* Ch = path ? xru : xrg;
    const int colBase = grp * 128;

    // load+convert: thread covers row=tid>>1, 64 cols (side = tid&1)
    {
        int row = tid >> 1, side = tid & 1;
        const float* as = Af + (size_t)(m0 + row) * DIN + side * 64;
        const float* bs = Bf + (size_t)row * 128 + side * 64;
        uint32_t dstbase = (uint32_t)side * STAGE_H + (uint32_t)row * 64;
#pragma unroll
        for (int c = 0; c < 8; c++) {
            uint32_t off = dstbase + (uint32_t)((c ^ (row & 7)) * 8);
            float4 a0 = reinterpret_cast<const float4*>(as + c * 8)[0];
            float4 a1 = reinterpret_cast<const float4*>(as + c * 8)[1];
            uint4 oa;
            __half2 h;
            h = __floats2half2_rn(a0.x, a0.y); oa.x = *reinterpret_cast<uint32_t*>(&h);
            h = __floats2half2_rn(a0.z, a0.w); oa.y = *reinterpret_cast<uint32_t*>(&h);
            h = __floats2half2_rn(a1.x, a1.y); oa.z = *reinterpret_cast<uint32_t*>(&h);
            h = __floats2half2_rn(a1.z, a1.w); oa.w = *reinterpret_cast<uint32_t*>(&h);
            *reinterpret_cast<uint4*>(&At[off]) = oa;
            float4 b0 = reinterpret_cast<const float4*>(bs + c * 8)[0];
            float4 b1 = reinterpret_cast<const float4*>(bs + c * 8)[1];
            uint4 ob;
            h = __floats2half2_rn(b0.x, b0.y); ob.x = *reinterpret_cast<uint32_t*>(&h);
            h = __floats2half2_rn(b0.z, b0.w); ob.y = *reinterpret_cast<uint32_t*>(&h);
            h = __floats2half2_rn(b1.x, b1.y); ob.z = *reinterpret_cast<uint32_t*>(&h);
            h = __floats2half2_rn(b1.z, b1.w); ob.w = *reinterpret_cast<uint32_t*>(&h);
            *reinterpret_cast<uint4*>(&Bt[off]) = ob;
        }
    }
    __syncthreads();

    const int lane = tid & 31, wid = tid >> 5;
    const int wm = wid >> 2, wn = wid & 3;

    float acc[4][4][4];
#pragma unroll
    for (int i = 0; i < 4; i++)
#pragma unroll
        for (int jj = 0; jj < 4; jj++)
#pragma unroll
            for (int k = 0; k < 4; k++) acc[i][jj][k] = 0.f;

#pragma unroll
    for (int t2 = 0; t2 < 2; t2++) {
        const __half* as = At + t2 * STAGE_H;
        const __half* bs = Bt + t2 * STAGE_H;
#pragma unroll
        for (int kk = 0; kk < 4; kk++) {
            uint32_t af[4][4], bf[4][2];
#pragma unroll
            for (int mi = 0; mi < 4; mi++) {
                int ar = wm * 64 + mi * 16 + (lane & 15);
                int ch = kk * 2 + (lane >> 4);
                const __half* p = as + ar * 64 + ((ch ^ (ar & 7)) * 8);
                ldm4(af[mi][0], af[mi][1], af[mi][2], af[mi][3], p);
            }
#pragma unroll
            for (int nb = 0; nb < 2; nb++) {
                int br = wn * 32 + nb * 16 + (lane & 7) + ((lane >> 4) << 3);
                int ch = kk * 2 + ((lane >> 3) & 1);
                const __half* p = bs + br * 64 + ((ch ^ (br & 7)) * 8);
                uint32_t q0, q1, q2, q3;
                ldm4(q0, q1, q2, q3, p);
                bf[nb * 2][0] = q0; bf[nb * 2][1] = q1;
                bf[nb * 2 + 1][0] = q2; bf[nb * 2 + 1][1] = q3;
            }
#pragma unroll
            for (int mi = 0; mi < 4; mi++)
#pragma unroll
                for (int ni = 0; ni < 4; ni++)
                    mma16816(acc[mi][ni], af[mi], bf[ni]);
        }
    }

    const int crow = wm * 64 + (lane >> 2);
    const int ccol = wn * 32 + (lane & 3) * 2;
#pragma unroll
    for (int mi = 0; mi < 4; mi++) {
#pragma unroll
        for (int ni = 0; ni < 4; ni++) {
            int gr = m0 + crow + mi * 16;
            int gc = colBase + ccol + ni * 8;
            *reinterpret_cast<__half2*>(&Ch[(size_t)gr * DIN + gc]) =
                __floats2half2_rn(acc[mi][ni][0], acc[mi][ni][1]);
            *reinterpret_cast<__half2*>(&Ch[(size_t)(gr + 8) * DIN + gc]) =
                __floats2half2_rn(acc[mi][ni][2], acc[mi][ni][3]);
        }
    }
}

// ---------------- host ----------------
template<typename T>
static void* symaddr(T& sym_) {
    void* p = nullptr;
    cudaGetSymbolAddress(&p, sym_);
    return p;
}

extern "C" void kernel_launch(void* const* d_in, const int* in_sizes, int n_in,
                              void* d_out, int out_size) {
    (void)in_sizes; (void)n_in; (void)out_size;
    const float* x     = (const float*)d_in[0];
    const float* cb    = (const float*)d_in[1];
    const float* gnorm = (const float*)d_in[2];
    const float* gbias = (const float*)d_in[3];
    const float* unorm = (const float*)d_in[4];
    const float* ubias = (const float*)d_in[5];
    const float* dnorm = (const float*)d_in[6];
    const float* dbias = (const float*)d_in[7];
    const float* rotg  = (const float*)d_in[8];
    const float* rotu  = (const float*)d_in[9];
    const float* rotd  = (const float*)d_in[10];
    const int*   gp    = (const int*)d_in[11];
    const int*   up_   = (const int*)d_in[12];
    const int*   dp    = (const int*)d_in[13];
    float* out = (float*)d_out;

    __half* rdh   = (__half*)symaddr(g_rotd_h);
    __half* Wg    = (__half*)symaddr(g_Wg);
    __half* Wu    = (__half*)symaddr(g_Wu);
    __half* Wd    = (__half*)symaddr(g_Wd);
    __half* xrg   = (__half*)symaddr(g_xrg);
    __half* xru   = (__half*)symaddr(g_xru);
    __half* gateh = (__half*)symaddr(g_gate);
    __half* hr    = (__half*)symaddr(g_hr);
    float*  part  = (float*)symaddr(g_part);

    const int TPB = 256;
    cudaFuncSetAttribute(k_gemm<4>,  cudaFuncAttributeMaxDynamicSharedMemorySize, SMEM_G2);
    cudaFuncSetAttribute(k_gate_mix, cudaFuncAttributeMaxDynamicSharedMemorySize, SMEM_G2);
    cudaFuncSetAttribute(k_uprot,    cudaFuncAttributeMaxDynamicSharedMemorySize, SMEM_G2);
    cudaFuncSetAttribute(k_phase1,   cudaFuncAttributeMaxDynamicSharedMemorySize, SMEM_G2);

    // phase 1: x-rotations (inline fp32 converts) + Wg dequant + rotd convert
    k_phase1<<<256 + DQ_BPM + CVT_BPM, TPB, SMEM_G2>>>(
        x, rotg, rotu, xrg, xru, gp, cb, gnorm, Wg, rotd, rdh);

    // gate GEMM + Wu/Wd dequant hidden behind it
    k_gate_mix<<<512 + 2 * DQ_BPM, TPB, SMEM_G2>>>(
        xrg, Wg, gbias, gateh, up_, dp, cb, unorm, dnorm, Wu, Wd);

    // fused: u-GEMM + SwiGLU + per-group h rotation -> hr directly
    k_uprot<<<dim3(BB / 128, DINT / 128), 256, SMEM_G2>>>(
        xru, Wu, ubias, gateh, rdh, hr);

    // down GEMM split-K=2
    k_gemm<4><<<dim3(BB / 128, DIN / 128, 2), 256, SMEM_G2>>>(
        hr, Wd, nullptr, nullptr, part, BB, DIN, DINT / 2, DINT, DINT, DIN,
        DINT / 2, DINT / 2, 0, BB * DIN);

    // out = part0 + part1 + dbias
    {
        int n4r = BB * DIN / 4;
        k_reduce2<<<(n4r + TPB - 1) / TPB, TPB>>>(
            (const float4*)part, (const float4*)(part + BB * DIN), dbias,
            (float4*)out, n4r, DIN / 4);
    }
}